// round 15
// baseline (speedup 1.0000x reference)
#include <cuda_runtime.h>
#include <math.h>

#define NMAPS 32
#define CDIM 256
#define HW 4096          // 64*64
#define NCELLS 256       // 16*16 cells per map
#define NCHUNK 16        // split-K chunks (16 channels each)
#define THRESH 0.65f

// ---------------- device scratch (no allocations allowed) ----------------
__device__ float g_part[NCHUNK * NMAPS * HW];   // partial dots (ref un-normalized; deferred)
__device__ float g_ssp[NCHUNK * HW];            // partial per-pixel sum-of-squares
__device__ float g_sim[NMAPS * HW];             // pixel-normalized sims (rinv deferred)
__device__ float g_cell_score[NMAPS * NCELLS];
__device__ int   g_cell_idx[NMAPS * NCELLS];    // ly*64+lx within cell
__device__ float g_cmin_val[NMAPS * NCELLS];
__device__ int   g_cmin_idx[NMAPS * NCELLS];    // gy*1024+gx flat index
__device__ int   g_cnt[NMAPS];                  // ticket counters (zeroed by k_gemm)

// ---------------------------------------------------------------------------
// K1: split-K partial GEMM, 4 adjacent pixels x 4 refs per thread (measured
// ~4.0 us). grid = (32 pixel-tiles of 128, 16 chunks) = 512 blocks.
// ---------------------------------------------------------------------------
__global__ void k_gemm(const float* __restrict__ feat, const float* __restrict__ ref) {
    __shared__ __align__(16) float sref_t[16][32];    // [channel][ref]
    __shared__ __align__(16) float sfeat[16][128];    // [channel][pixel]
    int tid = threadIdx.x;
    int chunk = blockIdx.y;

    if (blockIdx.x == 0 && blockIdx.y == 0 && tid < NMAPS) g_cnt[tid] = 0;

    for (int i = tid; i < 16 * 32; i += 256) {
        int c = i >> 5, r = i & 31;
        sref_t[c][r] = ref[r * CDIM + chunk * 16 + c];
    }
    const float* fbase = feat + chunk * 16 * HW + blockIdx.x * 128;
    #pragma unroll
    for (int i = tid; i < 16 * 128; i += 256) {
        int c = i >> 7, p = i & 127;
        sfeat[c][p] = fbase[c * HW + p];             // coalesced 512B rows
    }
    __syncthreads();

    int lane = tid & 31;
    int rg = tid >> 5;                   // warp-uniform ref group
    int px = 4 * lane;                   // pixels px..px+3

    float4 A0 = {0,0,0,0}, A1 = {0,0,0,0}, A2 = {0,0,0,0}, A3 = {0,0,0,0};
    float4 SS = {0,0,0,0};
    #pragma unroll
    for (int c = 0; c < 16; c++) {
        float4 v = *reinterpret_cast<const float4*>(&sfeat[c][px]);        // LDS.128
        float4 r4 = *reinterpret_cast<const float4*>(&sref_t[c][rg * 4]);  // broadcast LDS.128
        SS.x = fmaf(v.x, v.x, SS.x); SS.y = fmaf(v.y, v.y, SS.y);
        SS.z = fmaf(v.z, v.z, SS.z); SS.w = fmaf(v.w, v.w, SS.w);
        A0.x = fmaf(r4.x, v.x, A0.x); A0.y = fmaf(r4.x, v.y, A0.y);
        A0.z = fmaf(r4.x, v.z, A0.z); A0.w = fmaf(r4.x, v.w, A0.w);
        A1.x = fmaf(r4.y, v.x, A1.x); A1.y = fmaf(r4.y, v.y, A1.y);
        A1.z = fmaf(r4.y, v.z, A1.z); A1.w = fmaf(r4.y, v.w, A1.w);
        A2.x = fmaf(r4.z, v.x, A2.x); A2.y = fmaf(r4.z, v.y, A2.y);
        A2.z = fmaf(r4.z, v.z, A2.z); A2.w = fmaf(r4.z, v.w, A2.w);
        A3.x = fmaf(r4.w, v.x, A3.x); A3.y = fmaf(r4.w, v.y, A3.y);
        A3.z = fmaf(r4.w, v.z, A3.z); A3.w = fmaf(r4.w, v.w, A3.w);
    }
    int pix = blockIdx.x * 128 + px;
    float* po = g_part + (chunk * NMAPS + rg * 4) * HW + pix;
    *reinterpret_cast<float4*>(po)          = A0;    // STG.128
    *reinterpret_cast<float4*>(po + HW)     = A1;
    *reinterpret_cast<float4*>(po + 2 * HW) = A2;
    *reinterpret_cast<float4*>(po + 3 * HW) = A3;
    if (rg == 0)
        *reinterpret_cast<float4*>(&g_ssp[chunk * HW + pix]) = SS;
}

// ---------------------------------------------------------------------------
// K1b: combine split-K partials + per-pixel norm (R10-proven shape).
// grid = (16 px-tiles, 8 map-groups) = 128 blocks, 256 thr. Thread: 1 pixel,
// pinv once, 4 maps. Every partial read exactly once; 80 independent LDGs.
// ---------------------------------------------------------------------------
__global__ void k_combine() {
    int pix = blockIdx.x * 256 + threadIdx.x;
    int m0 = blockIdx.y * 4;
    float ss = 0.f;
    #pragma unroll
    for (int c = 0; c < NCHUNK; c++) ss += g_ssp[c * HW + pix];
    float pinv = 1.0f / (sqrtf(ss) + 1e-12f);
    #pragma unroll
    for (int k = 0; k < 4; k++) {
        int m = m0 + k;
        float d = 0.f;
        #pragma unroll
        for (int c = 0; c < NCHUNK; c++) d += g_part[(c * NMAPS + m) * HW + pix];
        g_sim[m * HW + pix] = d * pinv;
    }
}

// ---------------------------------------------------------------------------
// K2: per-cell minimax + ticketed per-map sort. grid = (16 cy-rows, 32 maps),
// 512 threads.
//   phase 1: 384 threads load the 6x64 sim row-tile (ONE load each)
//   phase 2: warp=cell endpoint-trick max/min with indices -> g_cell_*
//   phase 3: __threadfence + per-map ticket; ticket 15 proceeds
//   phase 4 (one block per map): low 256 = points sort, high 256 = bg.
// ---------------------------------------------------------------------------
#define EP_SEG(R0, R1, TA, TB, OYA, OYB) {                                    \
    float _d = (R1) - (R0);                                                   \
    float _va = fmaf((TA), _d, (R0)), _vb = fmaf((TB), _d, (R0));             \
    float _mx; int _mxo; float _mn; int _mno;                                 \
    if (_vb > _va) { _mx = _vb; _mxo = (OYB); } else { _mx = _va; _mxo = (OYA); } \
    if (_vb < _va) { _mn = _vb; _mno = (OYB); } else { _mn = _va; _mno = (OYA); } \
    if (_mx > bestv) { bestv = _mx; bestoy = _mxo; }                          \
    if (_mn < minv)  { minv  = _mn; minoy  = _mno; } }

#define EP_ONE(V, OY) { float _v = (V);                                       \
    if (_v > bestv) { bestv = _v; bestoy = (OY); }                            \
    if (_v < minv)  { minv  = _v; minoy  = (OY); } }

__global__ __launch_bounds__(512) void k_cells(float* __restrict__ out,
                                               const float* __restrict__ ref) {
    int cy = blockIdx.x;
    int m  = blockIdx.y;
    int tid = threadIdx.x;
    int lane = tid & 31;

    __shared__ __align__(16) float tile[6][64];    // sim rows 4cy-1..4cy+4 (clamped)

    // ---- phase 1: load row tile from g_sim (single LDG per thread) ----
    if (tid < 384) {
        int row = tid >> 6, colc = tid & 63;
        int sr = min(max(4 * cy - 1 + row, 0), 63);
        tile[row][colc] = g_sim[m * HW + sr * 64 + colc];
    }
    __syncthreads();

    // ---- phase 2: per-cell (warp) endpoint minimax ----
    {
        int cx = tid >> 5;
        int cyc = (cy == 0) ? 0 : ((cy == 15) ? 2 : 1);

        float colBest[2]; int colBoy[2];
        float colMin[2];  int colMoy[2];

        #pragma unroll
        for (int h = 0; h < 2; h++) {
            int gx = cx * 64 + lane + h * 32;
            float fx = ((float)gx - 7.5f) * 0.0625f;
            int jx = (int)floorf(fx);
            jx = min(max(jx, 0), 62);
            float tx = fminf(fmaxf(fx - (float)jx, 0.f), 1.f);
            float wx0 = 1.0f - tx;
            float v0 = wx0 * tile[0][jx] + tx * tile[0][jx + 1];
            float v1 = wx0 * tile[1][jx] + tx * tile[1][jx + 1];
            float v2 = wx0 * tile[2][jx] + tx * tile[2][jx + 1];
            float v3 = wx0 * tile[3][jx] + tx * tile[3][jx + 1];
            float v4 = wx0 * tile[4][jx] + tx * tile[4][jx + 1];
            float v5 = wx0 * tile[5][jx] + tx * tile[5][jx + 1];

            float bestv = -1e30f; int bestoy = 0;
            float minv  =  1e30f; int minoy  = 0;
            if (cyc == 0) {
                EP_ONE(v1, 0);
                EP_SEG(v1, v2, 0.03125f, 0.96875f, 8, 23);
                EP_SEG(v2, v3, 0.03125f, 0.96875f, 24, 39);
                EP_SEG(v3, v4, 0.03125f, 0.96875f, 40, 55);
                EP_SEG(v4, v5, 0.03125f, 0.46875f, 56, 63);
            } else if (cyc == 2) {
                EP_SEG(v0, v1, 0.53125f, 0.96875f, 0, 7);
                EP_SEG(v1, v2, 0.03125f, 0.96875f, 8, 23);
                EP_SEG(v2, v3, 0.03125f, 0.96875f, 24, 39);
                EP_SEG(v3, v4, 0.03125f, 0.96875f, 40, 55);
                EP_ONE(v4, 56);
            } else {
                EP_SEG(v0, v1, 0.53125f, 0.96875f, 0, 7);
                EP_SEG(v1, v2, 0.03125f, 0.96875f, 8, 23);
                EP_SEG(v2, v3, 0.03125f, 0.96875f, 24, 39);
                EP_SEG(v3, v4, 0.03125f, 0.96875f, 40, 55);
                EP_SEG(v4, v5, 0.03125f, 0.46875f, 56, 63);
            }
            colBest[h] = bestv; colBoy[h] = bestoy;
            colMin[h]  = minv;  colMoy[h] = minoy;
        }

        float bestv = colBest[0]; int bidx = colBoy[0] * 64 + lane;
        {
            int i2 = colBoy[1] * 64 + lane + 32;
            if (colBest[1] > bestv || (colBest[1] == bestv && i2 < bidx)) { bestv = colBest[1]; bidx = i2; }
        }
        float minv = colMin[0];
        int midx = ((cy * 64 + colMoy[0]) << 10) + cx * 64 + lane;
        {
            int i2 = ((cy * 64 + colMoy[1]) << 10) + cx * 64 + lane + 32;
            if (colMin[1] < minv || (colMin[1] == minv && i2 < midx)) { minv = colMin[1]; midx = i2; }
        }

        #pragma unroll
        for (int off = 16; off; off >>= 1) {
            float ov = __shfl_down_sync(0xFFFFFFFFu, bestv, off);
            int   oi = __shfl_down_sync(0xFFFFFFFFu, bidx, off);
            if (ov > bestv || (ov == bestv && oi < bidx)) { bestv = ov; bidx = oi; }
            float mv = __shfl_down_sync(0xFFFFFFFFu, minv, off);
            int   mi = __shfl_down_sync(0xFFFFFFFFu, midx, off);
            if (mv < minv || (mv == minv && mi < midx)) { minv = mv; midx = mi; }
        }
        if (lane == 0) {
            int cell = cy * 16 + cx;
            g_cell_score[m * NCELLS + cell] = bestv;
            g_cell_idx[m * NCELLS + cell]   = bidx;
            g_cmin_val[m * NCELLS + cell]   = minv;
            g_cmin_idx[m * NCELLS + cell]   = midx;
        }
    }

    // ---- phase 3: ticket (threadfence-reduction pattern) ----
    __threadfence();
    __syncthreads();
    __shared__ int s_t;
    if (tid == 0) s_t = atomicAdd(&g_cnt[m], 1);
    __syncthreads();
    if (s_t != 15) return;    // only the last-finishing block of this map sorts

    // ---- phase 4: per-map sort + bg ----
    __shared__ __align__(16) float skey[256];
    __shared__ float red[8];
    __shared__ int wcnt[8];
    __shared__ float bgv[8]; __shared__ int bgi[8];
    __shared__ float s_rinv;

    int w = tid >> 5;
    bool lo = tid < 256;

    float myscore = 0.f; int myidx = 0;
    float mymin = 0.f;   int mymini = 0;
    if (lo) {
        float v = ref[m * CDIM + tid];
        float p = v * v;
        #pragma unroll
        for (int off = 16; off; off >>= 1) p += __shfl_down_sync(0xFFFFFFFFu, p, off);
        if (lane == 0) red[w] = p;
        myscore = g_cell_score[m * NCELLS + tid];
        myidx   = g_cell_idx[m * NCELLS + tid];
    } else {
        int cell = (w - 8) * 32 + lane;
        mymin  = g_cmin_val[m * NCELLS + cell];
        mymini = g_cmin_idx[m * NCELLS + cell];
        #pragma unroll
        for (int off = 16; off; off >>= 1) {
            float ov = __shfl_down_sync(0xFFFFFFFFu, mymin, off);
            int   oi = __shfl_down_sync(0xFFFFFFFFu, mymini, off);
            if (ov < mymin || (ov == mymin && oi < mymini)) { mymin = ov; mymini = oi; }
        }
        if (lane == 0) { bgv[w - 8] = mymin; bgi[w - 8] = mymini; }
    }
    __syncthreads();
    if (tid == 0) {
        float s = 0.f;
        #pragma unroll
        for (int i = 0; i < 8; i++) s += red[i];
        s_rinv = 1.0f / (sqrtf(s) + 1e-12f);
    }
    __syncthreads();

    if (lo) {
        float rinv = s_rinv;
        float score = myscore * rinv;
        bool valid = score > THRESH;
        float key = valid ? score : -1.0f;
        skey[tid] = key;
        unsigned bal = __ballot_sync(0xFFFFFFFFu, valid);
        if (lane == 0) wcnt[w] = __popc(bal);
        __syncthreads();

        int nvalid = 0, beforeW = 0;
        #pragma unroll
        for (int i = 0; i < 8; i++) {
            int c = wcnt[i];
            nvalid += c;
            if (i < w) beforeW += c;
        }
        int validBefore = beforeW + __popc(bal & ((1u << lane) - 1u));

        int rank;
        if (!valid) {
            rank = nvalid + (tid - validBefore);        // stable among equal -1 keys
        } else {
            rank = 0;                                   // rare path: full stable count
            const float4* sk4 = reinterpret_cast<const float4*>(skey);
            #pragma unroll 8
            for (int q = 0; q < 64; q++) {
                float4 kk = sk4[q];
                int j = q * 4;
                rank += (kk.x > key) || (kk.x == key && (j + 0) < tid);
                rank += (kk.y > key) || (kk.y == key && (j + 1) < tid);
                rank += (kk.z > key) || (kk.z == key && (j + 2) < tid);
                rank += (kk.w > key) || (kk.w == key && (j + 3) < tid);
            }
        }

        int ccy = tid >> 4, ccx = tid & 15;
        int ly = myidx >> 6, lx = myidx & 63;
        float* po = out + m * (NCELLS * 3) + rank * 3;
        po[0] = valid ? (float)(ccx * 64 + lx) : -1.0f;
        po[1] = valid ? (float)(ccy * 64 + ly) : -1.0f;
        po[2] = valid ? score : -1.0f;
    } else {
        __syncthreads();   // matches the lo-half barrier after skey/wcnt
        if (tid == 256) {
            float mv = bgv[0]; int mi = bgi[0];
            #pragma unroll
            for (int i = 1; i < 8; i++) {
                if (bgv[i] < mv || (bgv[i] == mv && bgi[i] < mi)) { mv = bgv[i]; mi = bgi[i]; }
            }
            float* pb = out + NMAPS * NCELLS * 3 + m * 2;
            pb[0] = (float)(mi & 1023);   // x = col
            pb[1] = (float)(mi >> 10);    // y = row
        }
    }
}

// ---------------------------------------------------------------------------
extern "C" void kernel_launch(void* const* d_in, const int* in_sizes, int n_in,
                              void* d_out, int out_size) {
    const float* feat = (const float*)d_in[0];  // [1,256,64,64]
    const float* ref  = (const float*)d_in[1];  // [32,1,256]
    if (n_in >= 2 && in_sizes[0] == NMAPS * CDIM) {  // defensive: order by size
        ref  = (const float*)d_in[0];
        feat = (const float*)d_in[1];
    }
    (void)out_size;

    dim3 g1(32, NCHUNK);
    k_gemm<<<g1, 256>>>(feat, ref);
    dim3 g1b(16, 8);
    k_combine<<<g1b, 256>>>();
    dim3 g2(16, NMAPS);
    k_cells<<<g2, 512>>>((float*)d_out, ref);
}

// round 16
// speedup vs baseline: 1.1235x; 1.1235x over previous
#include <cuda_runtime.h>
#include <math.h>

#define NMAPS 32
#define CDIM 256
#define HW 4096          // 64*64
#define NCELLS 256       // 16*16 cells per map
#define NCHUNK 16        // split-K chunks (16 channels each)
#define THRESH 0.65f

// ---------------- device scratch (no allocations allowed) ----------------
__device__ float g_part[NCHUNK * NMAPS * HW];   // partial dots (ref un-normalized; deferred)
__device__ float g_ssp[NCHUNK * HW];            // partial per-pixel sum-of-squares
__device__ float g_pinv[HW];                    // per-pixel 1/(||feat||+eps)
__device__ float g_cell_score[NMAPS * NCELLS];
__device__ int   g_cell_idx[NMAPS * NCELLS];    // ly*64+lx within cell
__device__ float g_cmin_val[NMAPS * NCELLS];
__device__ int   g_cmin_idx[NMAPS * NCELLS];    // gy*1024+gx flat index
__device__ int   g_cnt[NMAPS];                  // ticket counters (zeroed by k_gemm)

// ---------------------------------------------------------------------------
// K1: split-K partial GEMM (R11-proven: 2 adjacent pixels x 4 refs, 16 chunks,
// grid (64, 16) = 1024 blocks, 256 threads, regs 32).
// ---------------------------------------------------------------------------
__global__ void k_gemm(const float* __restrict__ feat, const float* __restrict__ ref) {
    __shared__ __align__(16) float sref_t[16][32];   // [channel][ref]
    __shared__ __align__(16) float sfeat[16][64];    // [channel][pixel]
    int tid = threadIdx.x;
    int chunk = blockIdx.y;

    if (blockIdx.x == 0 && blockIdx.y == 0 && tid < NMAPS) g_cnt[tid] = 0;

    for (int i = tid; i < 16 * 32; i += 256) {
        int c = i >> 5, r = i & 31;
        sref_t[c][r] = ref[r * CDIM + chunk * 16 + c];
    }
    const float* fbase = feat + chunk * 16 * HW + blockIdx.x * 64;
    #pragma unroll
    for (int i = tid; i < 16 * 64; i += 256) {
        int c = i >> 6, p = i & 63;
        sfeat[c][p] = fbase[c * HW + p];
    }
    __syncthreads();

    int lane = tid & 31;
    int rg = tid >> 5;                   // warp-uniform ref group
    int px = 2 * lane;                   // pixels px, px+1

    float a0 = 0.f, a1 = 0.f, a2 = 0.f, a3 = 0.f;
    float b0 = 0.f, b1 = 0.f, b2 = 0.f, b3 = 0.f;
    float ss0 = 0.f, ss1 = 0.f;
    #pragma unroll
    for (int c = 0; c < 16; c++) {
        float2 v = *reinterpret_cast<const float2*>(&sfeat[c][px]);        // LDS.64
        float4 r4 = *reinterpret_cast<const float4*>(&sref_t[c][rg * 4]);  // broadcast LDS.128
        ss0 += v.x * v.x;  ss1 += v.y * v.y;
        a0 = fmaf(r4.x, v.x, a0);  b0 = fmaf(r4.x, v.y, b0);
        a1 = fmaf(r4.y, v.x, a1);  b1 = fmaf(r4.y, v.y, b1);
        a2 = fmaf(r4.z, v.x, a2);  b2 = fmaf(r4.z, v.y, b2);
        a3 = fmaf(r4.w, v.x, a3);  b3 = fmaf(r4.w, v.y, b3);
    }
    int pix = blockIdx.x * 64 + px;
    float* po = g_part + (chunk * NMAPS + rg * 4) * HW + pix;
    *reinterpret_cast<float2*>(po)          = make_float2(a0, b0);
    *reinterpret_cast<float2*>(po + HW)     = make_float2(a1, b1);
    *reinterpret_cast<float2*>(po + 2 * HW) = make_float2(a2, b2);
    *reinterpret_cast<float2*>(po + 3 * HW) = make_float2(a3, b3);
    if (rg == 0)
        *reinterpret_cast<float2*>(&g_ssp[chunk * HW + pix]) = make_float2(ss0, ss1);
}

// ---------------------------------------------------------------------------
// K1b: per-pixel pinv (tiny: 16 blocks x 256 thr). Each ssp partial read
// exactly once; kills the 32x ssp redundancy + per-thread sqrt in k_epi.
// ---------------------------------------------------------------------------
__global__ void k_pinv() {
    int pix = blockIdx.x * 256 + threadIdx.x;
    float ss = 0.f;
    #pragma unroll
    for (int c = 0; c < NCHUNK; c++) ss += g_ssp[c * HW + pix];
    g_pinv[pix] = 1.0f / (sqrtf(ss) + 1e-12f);
}

// ---------------------------------------------------------------------------
// K2 (epilogue): fused combine + per-cell minimax + ticketed per-map sort.
// grid = (16 cy-rows, 32 maps), 512 threads.
//   phase 1: 384 threads: sum 16 dot-partials + 1 pinv load per pixel
//   phase 2: warp=cell endpoint-trick max/min with indices -> g_cell_*
//   phase 3: __threadfence + per-map ticket; ticket 15 proceeds
//   phase 4 (one block per map): low 256 = points sort, high 256 = bg.
// ---------------------------------------------------------------------------
#define EP_SEG(R0, R1, TA, TB, OYA, OYB) {                                    \
    float _d = (R1) - (R0);                                                   \
    float _va = fmaf((TA), _d, (R0)), _vb = fmaf((TB), _d, (R0));             \
    float _mx; int _mxo; float _mn; int _mno;                                 \
    if (_vb > _va) { _mx = _vb; _mxo = (OYB); } else { _mx = _va; _mxo = (OYA); } \
    if (_vb < _va) { _mn = _vb; _mno = (OYB); } else { _mn = _va; _mno = (OYA); } \
    if (_mx > bestv) { bestv = _mx; bestoy = _mxo; }                          \
    if (_mn < minv)  { minv  = _mn; minoy  = _mno; } }

#define EP_ONE(V, OY) { float _v = (V);                                       \
    if (_v > bestv) { bestv = _v; bestoy = (OY); }                            \
    if (_v < minv)  { minv  = _v; minoy  = (OY); } }

__global__ __launch_bounds__(512) void k_epi(float* __restrict__ out,
                                             const float* __restrict__ ref) {
    int cy = blockIdx.x;
    int m  = blockIdx.y;
    int tid = threadIdx.x;
    int lane = tid & 31;

    __shared__ __align__(16) float tile[6][64];    // sim rows 4cy-1..4cy+4 (clamped)

    // ---- phase 1: combine dot partials, scale by precomputed pinv ----
    if (tid < 384) {
        int row = tid >> 6, colc = tid & 63;
        int sr = min(max(4 * cy - 1 + row, 0), 63);
        int pix = sr * 64 + colc;
        float d = 0.f;
        #pragma unroll
        for (int c = 0; c < NCHUNK; c++) d += g_part[(c * NMAPS + m) * HW + pix];
        tile[row][colc] = d * g_pinv[pix];
    }
    __syncthreads();

    // ---- phase 2: per-cell (warp) endpoint minimax ----
    {
        int cx = tid >> 5;
        int cyc = (cy == 0) ? 0 : ((cy == 15) ? 2 : 1);

        float colBest[2]; int colBoy[2];
        float colMin[2];  int colMoy[2];

        #pragma unroll
        for (int h = 0; h < 2; h++) {
            int gx = cx * 64 + lane + h * 32;
            float fx = ((float)gx - 7.5f) * 0.0625f;
            int jx = (int)floorf(fx);
            jx = min(max(jx, 0), 62);
            float tx = fminf(fmaxf(fx - (float)jx, 0.f), 1.f);
            float wx0 = 1.0f - tx;
            float v0 = wx0 * tile[0][jx] + tx * tile[0][jx + 1];
            float v1 = wx0 * tile[1][jx] + tx * tile[1][jx + 1];
            float v2 = wx0 * tile[2][jx] + tx * tile[2][jx + 1];
            float v3 = wx0 * tile[3][jx] + tx * tile[3][jx + 1];
            float v4 = wx0 * tile[4][jx] + tx * tile[4][jx + 1];
            float v5 = wx0 * tile[5][jx] + tx * tile[5][jx + 1];

            float bestv = -1e30f; int bestoy = 0;
            float minv  =  1e30f; int minoy  = 0;
            if (cyc == 0) {
                EP_ONE(v1, 0);
                EP_SEG(v1, v2, 0.03125f, 0.96875f, 8, 23);
                EP_SEG(v2, v3, 0.03125f, 0.96875f, 24, 39);
                EP_SEG(v3, v4, 0.03125f, 0.96875f, 40, 55);
                EP_SEG(v4, v5, 0.03125f, 0.46875f, 56, 63);
            } else if (cyc == 2) {
                EP_SEG(v0, v1, 0.53125f, 0.96875f, 0, 7);
                EP_SEG(v1, v2, 0.03125f, 0.96875f, 8, 23);
                EP_SEG(v2, v3, 0.03125f, 0.96875f, 24, 39);
                EP_SEG(v3, v4, 0.03125f, 0.96875f, 40, 55);
                EP_ONE(v4, 56);
            } else {
                EP_SEG(v0, v1, 0.53125f, 0.96875f, 0, 7);
                EP_SEG(v1, v2, 0.03125f, 0.96875f, 8, 23);
                EP_SEG(v2, v3, 0.03125f, 0.96875f, 24, 39);
                EP_SEG(v3, v4, 0.03125f, 0.96875f, 40, 55);
                EP_SEG(v4, v5, 0.03125f, 0.46875f, 56, 63);
            }
            colBest[h] = bestv; colBoy[h] = bestoy;
            colMin[h]  = minv;  colMoy[h] = minoy;
        }

        float bestv = colBest[0]; int bidx = colBoy[0] * 64 + lane;
        {
            int i2 = colBoy[1] * 64 + lane + 32;
            if (colBest[1] > bestv || (colBest[1] == bestv && i2 < bidx)) { bestv = colBest[1]; bidx = i2; }
        }
        float minv = colMin[0];
        int midx = ((cy * 64 + colMoy[0]) << 10) + cx * 64 + lane;
        {
            int i2 = ((cy * 64 + colMoy[1]) << 10) + cx * 64 + lane + 32;
            if (colMin[1] < minv || (colMin[1] == minv && i2 < midx)) { minv = colMin[1]; midx = i2; }
        }

        #pragma unroll
        for (int off = 16; off; off >>= 1) {
            float ov = __shfl_down_sync(0xFFFFFFFFu, bestv, off);
            int   oi = __shfl_down_sync(0xFFFFFFFFu, bidx, off);
            if (ov > bestv || (ov == bestv && oi < bidx)) { bestv = ov; bidx = oi; }
            float mv = __shfl_down_sync(0xFFFFFFFFu, minv, off);
            int   mi = __shfl_down_sync(0xFFFFFFFFu, midx, off);
            if (mv < minv || (mv == minv && mi < midx)) { minv = mv; midx = mi; }
        }
        if (lane == 0) {
            int cell = cy * 16 + cx;
            g_cell_score[m * NCELLS + cell] = bestv;
            g_cell_idx[m * NCELLS + cell]   = bidx;
            g_cmin_val[m * NCELLS + cell]   = minv;
            g_cmin_idx[m * NCELLS + cell]   = midx;
        }
    }

    // ---- phase 3: ticket (threadfence-reduction pattern) ----
    __threadfence();
    __syncthreads();
    __shared__ int s_t;
    if (tid == 0) s_t = atomicAdd(&g_cnt[m], 1);
    __syncthreads();
    if (s_t != 15) return;    // only the last-finishing block of this map sorts

    // ---- phase 4: per-map sort + bg ----
    __shared__ __align__(16) float skey[256];
    __shared__ float red[8];
    __shared__ int wcnt[8];
    __shared__ float bgv[8]; __shared__ int bgi[8];
    __shared__ float s_rinv;

    int w = tid >> 5;
    bool lo = tid < 256;

    float myscore = 0.f; int myidx = 0;
    float mymin = 0.f;   int mymini = 0;
    if (lo) {
        float v = ref[m * CDIM + tid];
        float p = v * v;
        #pragma unroll
        for (int off = 16; off; off >>= 1) p += __shfl_down_sync(0xFFFFFFFFu, p, off);
        if (lane == 0) red[w] = p;
        myscore = g_cell_score[m * NCELLS + tid];
        myidx   = g_cell_idx[m * NCELLS + tid];
    } else {
        int cell = (w - 8) * 32 + lane;
        mymin  = g_cmin_val[m * NCELLS + cell];
        mymini = g_cmin_idx[m * NCELLS + cell];
        #pragma unroll
        for (int off = 16; off; off >>= 1) {
            float ov = __shfl_down_sync(0xFFFFFFFFu, mymin, off);
            int   oi = __shfl_down_sync(0xFFFFFFFFu, mymini, off);
            if (ov < mymin || (ov == mymin && oi < mymini)) { mymin = ov; mymini = oi; }
        }
        if (lane == 0) { bgv[w - 8] = mymin; bgi[w - 8] = mymini; }
    }
    __syncthreads();
    if (tid == 0) {
        float s = 0.f;
        #pragma unroll
        for (int i = 0; i < 8; i++) s += red[i];
        s_rinv = 1.0f / (sqrtf(s) + 1e-12f);
    }
    __syncthreads();

    if (lo) {
        float rinv = s_rinv;
        float score = myscore * rinv;
        bool valid = score > THRESH;
        float key = valid ? score : -1.0f;
        skey[tid] = key;
        unsigned bal = __ballot_sync(0xFFFFFFFFu, valid);
        if (lane == 0) wcnt[w] = __popc(bal);
        __syncthreads();

        int nvalid = 0, beforeW = 0;
        #pragma unroll
        for (int i = 0; i < 8; i++) {
            int c = wcnt[i];
            nvalid += c;
            if (i < w) beforeW += c;
        }
        int validBefore = beforeW + __popc(bal & ((1u << lane) - 1u));

        int rank;
        if (!valid) {
            rank = nvalid + (tid - validBefore);        // stable among equal -1 keys
        } else {
            rank = 0;                                   // rare path: full stable count
            const float4* sk4 = reinterpret_cast<const float4*>(skey);
            #pragma unroll 8
            for (int q = 0; q < 64; q++) {
                float4 kk = sk4[q];
                int j = q * 4;
                rank += (kk.x > key) || (kk.x == key && (j + 0) < tid);
                rank += (kk.y > key) || (kk.y == key && (j + 1) < tid);
                rank += (kk.z > key) || (kk.z == key && (j + 2) < tid);
                rank += (kk.w > key) || (kk.w == key && (j + 3) < tid);
            }
        }

        int ccy = tid >> 4, ccx = tid & 15;
        int ly = myidx >> 6, lx = myidx & 63;
        float* po = out + m * (NCELLS * 3) + rank * 3;
        po[0] = valid ? (float)(ccx * 64 + lx) : -1.0f;
        po[1] = valid ? (float)(ccy * 64 + ly) : -1.0f;
        po[2] = valid ? score : -1.0f;
    } else {
        __syncthreads();   // matches the lo-half barrier after skey/wcnt
        if (tid == 256) {
            float mv = bgv[0]; int mi = bgi[0];
            #pragma unroll
            for (int i = 1; i < 8; i++) {
                if (bgv[i] < mv || (bgv[i] == mv && bgi[i] < mi)) { mv = bgv[i]; mi = bgi[i]; }
            }
            float* pb = out + NMAPS * NCELLS * 3 + m * 2;
            pb[0] = (float)(mi & 1023);   // x = col
            pb[1] = (float)(mi >> 10);    // y = row
        }
    }
}

// ---------------------------------------------------------------------------
extern "C" void kernel_launch(void* const* d_in, const int* in_sizes, int n_in,
                              void* d_out, int out_size) {
    const float* feat = (const float*)d_in[0];  // [1,256,64,64]
    const float* ref  = (const float*)d_in[1];  // [32,1,256]
    if (n_in >= 2 && in_sizes[0] == NMAPS * CDIM) {  // defensive: order by size
        ref  = (const float*)d_in[0];
        feat = (const float*)d_in[1];
    }
    (void)out_size;

    dim3 g1(64, NCHUNK);
    k_gemm<<<g1, 256>>>(feat, ref);
    k_pinv<<<16, 256>>>();
    dim3 g2(16, NMAPS);
    k_epi<<<g2, 512>>>((float*)d_out, ref);
}